// round 13
// baseline (speedup 1.0000x reference)
#include <cuda_runtime.h>
#include <float.h>

#define DIM    256
#define BSEG   256
#define NSPLIT 4
#define CHUNKV 16
#define PITCH  260   // floats per SMEM row; conflict-free LDS patterns

// ---------------- scratch (static device arrays; no cudaMalloc) ----------------
__device__ int   segStartG[BSEG + 1];             // precomputed segment boundaries
__device__ float qsG[DIM];                        // scaled q
__device__ float qkGf[4 * DIM];                   // final qk, [d][h] interleaved
__device__ float accPartG[NSPLIT * BSEG * 1024];  // raw per-quarter sums, [b*4+q][h*256+d]
__device__ float denomPartG[NSPLIT * BSEG * 4];   // raw per-quarter denoms, [b*4+q][h]
__device__ float pooledG[BSEG * DIM];
__device__ float attnG[BSEG * DIM];

// ---------------- P0: segment boundaries (sorted ids -> start offsets) ----------------
__global__ __launch_bounds__(256) void seg_bounds(const int* __restrict__ seg, int N) {
    int i = blockIdx.x * 256 + threadIdx.x;
    if (i >= N) return;
    int s = seg[i];
    if (i == 0) {
        for (int b = 0; b <= s; b++) segStartG[b] = 0;
    } else {
        int p = seg[i - 1];
        if (p != s)
            for (int b = p + 1; b <= s; b++) segStartG[b] = i;
    }
    if (i == N - 1)
        for (int b = s + 1; b <= BSEG; b++) segStartG[b] = N;
}

// ---------------- P1: q = ((gq @ Wq^T) + bq) * (1/sqrt(64)) ----------------
__global__ __launch_bounds__(256) void prologue_q(const float* __restrict__ ipw,
                                                  const float* __restrict__ ipb,
                                                  const float* __restrict__ gq) {
    __shared__ float gqs[DIM];
    int t = threadIdx.x;
    gqs[t] = gq[t];
    __syncthreads();
    int w = t >> 5, l = t & 31;
    int row = blockIdx.x * 8 + w;
    float sum = 0.f;
#pragma unroll
    for (int k = l; k < DIM; k += 32) sum += ipw[row * DIM + k] * gqs[k];
#pragma unroll
    for (int off = 16; off; off >>= 1) sum += __shfl_xor_sync(0xffffffffu, sum, off);
    if (l == 0) qsG[row] = (sum + ipb[row]) * 0.125f;
}

// ---------------- P2: qk[h][d] = sum_{j<64} qs[h*64+j] * Wk[h*64+j][d] ----------------
// (score bias bk cancels in softmax normalization)
__global__ __launch_bounds__(256) void prologue_qk(const float* __restrict__ ipw) {
    int h = blockIdx.x;                 // 4 blocks
    __shared__ float qsl[64];
    int t = threadIdx.x;
    if (t < 64) qsl[t] = qsG[h * 64 + t];
    __syncthreads();
    const float* W = ipw + (size_t)(DIM + h * 64) * DIM;
    float a = 0.f;
#pragma unroll 16
    for (int j = 0; j < 64; j++) a += qsl[j] * W[j * DIM + t];
    qkGf[t * 4 + h] = a;
}

// ---------------- main: warp-autonomous + double-buffered prefetch -------------------
// No max subtraction (scores ~N(0,1): exp safe; max/bias cancel in normalization).
// Thread (w,l) owns dims {4l..4l+3, 128+4l..128+4l+3}; warp w owns nodes base+2w+j.
// X stays in registers; next chunk prefetched into Rb while current Ra computes.
__global__ __launch_bounds__(256, 2) void seg_kernel(const float* __restrict__ X) {
    __shared__ float4 fs[8][32][8];   // 32 KB: end-of-kernel cross-warp reduce
    __shared__ float4 sp[8][4][2];    // [warp][group][node] score partials
    __shared__ float4 es[8][2];       // [warp][node] e (heads)
    __shared__ float4 dsm[8];         // per-warp denom

    int t = threadIdx.x, w = t >> 5, l = t & 31;
    int bid = blockIdx.x;
    int b = bid >> 2, quar = bid & 3;

    const float4* Q4 = (const float4*)qkGf;
    float4 qlo[4], qhi[4];
#pragma unroll
    for (int c = 0; c < 4; c++) { qlo[c] = Q4[4 * l + c]; qhi[c] = Q4[128 + 4 * l + c]; }

    int sLo = segStartG[b], sHi = segStartG[b + 1];
    int cnt = sHi - sLo;
    int lo = sLo + (cnt * quar) / NSPLIT;
    int hi = sLo + (cnt * (quar + 1)) / NSPLIT;

    float4 accD[8];
#pragma unroll
    for (int k = 0; k < 8; k++) accD[k] = make_float4(0.f, 0.f, 0.f, 0.f);
    float4 dacc = make_float4(0.f, 0.f, 0.f, 0.f);
    float4 Ra[2][2], Rb[2][2];
#pragma unroll
    for (int j = 0; j < 2; j++) {
        Ra[j][0] = Ra[j][1] = make_float4(0.f, 0.f, 0.f, 0.f);
        Rb[j][0] = Rb[j][1] = make_float4(0.f, 0.f, 0.f, 0.f);
    }

    const float4* Xg = (const float4*)X;
    int n0 = 2 * w;

    int base = lo;
    int C = (hi > lo) ? min(CHUNKV, hi - lo) : 0;
    if (C > 0) {
#pragma unroll
        for (int j = 0; j < 2; j++) {
            int n = n0 + j;
            if (n < C) {
                Ra[j][0] = Xg[(size_t)(base + n) * 64 + l];
                Ra[j][1] = Xg[(size_t)(base + n) * 64 + 32 + l];
            }
        }
    }

    while (base < hi) {
        // ---- register score partials from Ra ----
        float4 ps[2];
#pragma unroll
        for (int j = 0; j < 2; j++) {
            float4 a = Ra[j][0], c4 = Ra[j][1];
            float4 s;
            s.x = a.x * qlo[0].x + a.y * qlo[1].x + a.z * qlo[2].x + a.w * qlo[3].x
                + c4.x * qhi[0].x + c4.y * qhi[1].x + c4.z * qhi[2].x + c4.w * qhi[3].x;
            s.y = a.x * qlo[0].y + a.y * qlo[1].y + a.z * qlo[2].y + a.w * qlo[3].y
                + c4.x * qhi[0].y + c4.y * qhi[1].y + c4.z * qhi[2].y + c4.w * qhi[3].y;
            s.z = a.x * qlo[0].z + a.y * qlo[1].z + a.z * qlo[2].z + a.w * qlo[3].z
                + c4.x * qhi[0].z + c4.y * qhi[1].z + c4.z * qhi[2].z + c4.w * qhi[3].z;
            s.w = a.x * qlo[0].w + a.y * qlo[1].w + a.z * qlo[2].w + a.w * qlo[3].w
                + c4.x * qhi[0].w + c4.y * qhi[1].w + c4.z * qhi[2].w + c4.w * qhi[3].w;
            ps[j] = s;
        }
        // ---- prefetch next chunk into Rb (latency hidden behind reduce/accumulate) ----
        int baseN = base + CHUNKV;
        int CN = 0;
        if (baseN < hi) {
            CN = min(CHUNKV, hi - baseN);
#pragma unroll
            for (int j = 0; j < 2; j++) {
                int n = n0 + j;
                if (n < CN) {
                    Rb[j][0] = Xg[(size_t)(baseN + n) * 64 + l];
                    Rb[j][1] = Xg[(size_t)(baseN + n) * 64 + 32 + l];
                }
            }
        }
        // ---- 3-round butterfly: lane l holds sum over lanes = l (mod 4) ----
#pragma unroll
        for (int j = 0; j < 2; j++) {
#pragma unroll
            for (int off = 16; off >= 4; off >>= 1) {
                ps[j].x += __shfl_xor_sync(0xffffffffu, ps[j].x, off);
                ps[j].y += __shfl_xor_sync(0xffffffffu, ps[j].y, off);
                ps[j].z += __shfl_xor_sync(0xffffffffu, ps[j].z, off);
                ps[j].w += __shfl_xor_sync(0xffffffffu, ps[j].w, off);
            }
        }
        if (l < 4) {
#pragma unroll
            for (int j = 0; j < 2; j++) sp[w][l][j] = ps[j];
        }
        __syncwarp();
        if (l < 2) {   // lane l finishes node n0+l
            float4 s0 = sp[w][0][l], s1 = sp[w][1][l], s2 = sp[w][2][l], s3 = sp[w][3][l];
            float4 e;
            if (n0 + l < C) {
                e.x = __expf(s0.x + s1.x + s2.x + s3.x);
                e.y = __expf(s0.y + s1.y + s2.y + s3.y);
                e.z = __expf(s0.z + s1.z + s2.z + s3.z);
                e.w = __expf(s0.w + s1.w + s2.w + s3.w);
                dacc.x += e.x; dacc.y += e.y; dacc.z += e.z; dacc.w += e.w;
            } else {
                e = make_float4(0.f, 0.f, 0.f, 0.f);
            }
            es[w][l] = e;
        }
        __syncwarp();
        // ---- accumulate: accD[dim] += e[node] * x[node][dim]  (e=0 masks stale Ra) ----
#pragma unroll
        for (int j = 0; j < 2; j++) {
            float4 e4 = es[w][j];          // broadcast LDS.128
            float4 a = Ra[j][0], c4 = Ra[j][1];
            accD[0].x += e4.x * a.x;  accD[0].y += e4.y * a.x;  accD[0].z += e4.z * a.x;  accD[0].w += e4.w * a.x;
            accD[1].x += e4.x * a.y;  accD[1].y += e4.y * a.y;  accD[1].z += e4.z * a.y;  accD[1].w += e4.w * a.y;
            accD[2].x += e4.x * a.z;  accD[2].y += e4.y * a.z;  accD[2].z += e4.z * a.z;  accD[2].w += e4.w * a.z;
            accD[3].x += e4.x * a.w;  accD[3].y += e4.y * a.w;  accD[3].z += e4.z * a.w;  accD[3].w += e4.w * a.w;
            accD[4].x += e4.x * c4.x; accD[4].y += e4.y * c4.x; accD[4].z += e4.z * c4.x; accD[4].w += e4.w * c4.x;
            accD[5].x += e4.x * c4.y; accD[5].y += e4.y * c4.y; accD[5].z += e4.z * c4.y; accD[5].w += e4.w * c4.y;
            accD[6].x += e4.x * c4.z; accD[6].y += e4.y * c4.z; accD[6].z += e4.z * c4.z; accD[6].w += e4.w * c4.z;
            accD[7].x += e4.x * c4.w; accD[7].y += e4.y * c4.w; accD[7].z += e4.z * c4.w; accD[7].w += e4.w * c4.w;
        }
        __syncwarp();   // protect sp/es before next chunk's writes
        // ---- rotate buffers ----
#pragma unroll
        for (int j = 0; j < 2; j++) { Ra[j][0] = Rb[j][0]; Ra[j][1] = Rb[j][1]; }
        base = baseN;
        C = CN;
    }

    // ---- cross-warp reduce (once) ----
#pragma unroll
    for (int k = 0; k < 8; k++) fs[w][l][k] = accD[k];
    // denom: lanes 0,1 hold node-slot partials; xor 1 combines
    dacc.x += __shfl_xor_sync(0xffffffffu, dacc.x, 1);
    dacc.y += __shfl_xor_sync(0xffffffffu, dacc.y, 1);
    dacc.z += __shfl_xor_sync(0xffffffffu, dacc.z, 1);
    dacc.w += __shfl_xor_sync(0xffffffffu, dacc.w, 1);
    if (l == 0) dsm[w] = dacc;
    __syncthreads();

    {   // thread t reduces dim d=t (all 4 heads) over 8 warps
        int li = (t & 127) >> 2, ci = t & 3, hf = t >> 7;
        float4 s = make_float4(0.f, 0.f, 0.f, 0.f);
#pragma unroll
        for (int w2 = 0; w2 < 8; w2++) {
            float4 v = fs[w2][li][hf * 4 + ci];
            s.x += v.x; s.y += v.y; s.z += v.z; s.w += v.w;
        }
        float* Ap = accPartG + (size_t)bid * 1024;
        Ap[0 * DIM + t] = s.x;
        Ap[1 * DIM + t] = s.y;
        Ap[2 * DIM + t] = s.z;
        Ap[3 * DIM + t] = s.w;
    }
    if (w == 0) {
        float4 v = (l < 8) ? dsm[l] : make_float4(0.f, 0.f, 0.f, 0.f);
#pragma unroll
        for (int off = 4; off; off >>= 1) {
            v.x += __shfl_xor_sync(0xffffffffu, v.x, off);
            v.y += __shfl_xor_sync(0xffffffffu, v.y, off);
            v.z += __shfl_xor_sync(0xffffffffu, v.z, off);
            v.w += __shfl_xor_sync(0xffffffffu, v.w, off);
        }
        if (l == 0) *(float4*)(denomPartG + bid * 4) = v;
    }
}

// ---------------- tiny GEMM: BM=8, BN=16, 2-way register split-K ----------------------
// mode 0: pooled = (sum of 4 quarter-partials, head-sliced)/denom @ Wv^T + bv
// mode 1: attn   = pooled @ Wo^T + opb
// mode 2: out    = attn @ Ww^T + ob  -> d_out
__global__ __launch_bounds__(256) void gemm_kernel(int mode,
                                                   const float* __restrict__ Wt,
                                                   const float* __restrict__ bias,
                                                   float* __restrict__ outp,
                                                   int Ncols) {
    __shared__ __align__(16) float As[8 * PITCH];    // 8.3 KB
    __shared__ __align__(16) float Ws[16 * PITCH];   // 16.6 KB
    int t = threadIdx.x;
    int c = t & 15, ks = (t >> 4) & 1, r = t >> 5;
    int nBase = blockIdx.x * 16, mBase = blockIdx.y * 8;

    if (mode == 0) {
        int hOff4 = (nBase >> 6) * 64;
#pragma unroll
        for (int i = 0; i < 2; i++) {
            int f = t + (i << 8);
            int m = f >> 6, k4 = f & 63;
            const float4* p0 = (const float4*)accPartG + (size_t)(mBase + m) * 1024 + hOff4 + k4;
            float4 a0 = p0[0], a1 = p0[256], a2 = p0[512], a3 = p0[768];
            float4 s = make_float4(a0.x + a1.x + a2.x + a3.x,
                                   a0.y + a1.y + a2.y + a3.y,
                                   a0.z + a1.z + a2.z + a3.z,
                                   a0.w + a1.w + a2.w + a3.w);
            *(float4*)(As + m * PITCH + 4 * k4) = s;
        }
    } else {
        const float* A = (mode == 1) ? pooledG : attnG;
#pragma unroll
        for (int i = 0; i < 2; i++) {
            int f = t + (i << 8);
            int m = f >> 6, k4 = f & 63;
            float4 a = ((const float4*)A)[(size_t)(mBase + m) * 64 + k4];
            *(float4*)(As + m * PITCH + 4 * k4) = a;
        }
    }
#pragma unroll
    for (int i = 0; i < 4; i++) {
        int f = t + (i << 8);
        int n = f >> 6, k4 = f & 63;
        float4 wv = ((const float4*)Wt)[(size_t)(nBase + n) * 64 + k4];
        *(float4*)(Ws + n * PITCH + 4 * k4) = wv;
    }
    __syncthreads();

    float acc = 0.f;
    int k0 = ks * 32;
#pragma unroll
    for (int k4 = 0; k4 < 32; k4++) {
        float4 a4 = *(const float4*)(As + r * PITCH + 4 * (k0 + k4));
        float4 w4 = *(const float4*)(Ws + c * PITCH + 4 * (k0 + k4));
        acc += a4.x * w4.x + a4.y * w4.y + a4.z * w4.z + a4.w * w4.w;
    }
    acc += __shfl_xor_sync(0xffffffffu, acc, 16);   // combine K halves

    if (ks == 0) {
        int row = mBase + r, col = nBase + c;
        if (mode == 0) {
            int h = nBase >> 6;
            float d = denomPartG[(row * 4 + 0) * 4 + h] + denomPartG[(row * 4 + 1) * 4 + h]
                    + denomPartG[(row * 4 + 2) * 4 + h] + denomPartG[(row * 4 + 3) * 4 + h];
            float inv = d > 0.f ? 1.f / d : 0.f;
            pooledG[row * DIM + col] = acc * inv + bias[col];
        } else if (mode == 1) {
            attnG[row * DIM + col] = acc + bias[col];
        } else {
            outp[(size_t)row * Ncols + col] = acc + bias[col];
        }
    }
}

// ---------------- launch (R12 resubmit #2: R10 hybrid unchanged; broker infra error) --
extern "C" void kernel_launch(void* const* d_in, const int* in_sizes, int n_in,
                              void* d_out, int out_size) {
    const float* node_feat = (const float*)d_in[0];
    const int*   segids    = (const int*)d_in[1];
    const float* gq        = (const float*)d_in[2];
    const float* ipw       = (const float*)d_in[3];
    const float* ipb       = (const float*)d_in[4];
    const float* opw       = (const float*)d_in[5];
    const float* opb       = (const float*)d_in[6];
    const float* ow        = (const float*)d_in[7];
    const float* ob        = (const float*)d_in[8];
    int N = in_sizes[0] / DIM;
    float* out = (float*)d_out;

    seg_bounds<<<(N + 255) / 256, 256>>>(segids, N);
    prologue_q<<<32, 256>>>(ipw, ipb, gq);
    prologue_qk<<<4, 256>>>(ipw);
    seg_kernel<<<NSPLIT * BSEG, 256>>>(node_feat);
    gemm_kernel<<<dim3(16, 32), 256>>>(0, ipw + 512 * 256, ipb + 512, out, 256);
    gemm_kernel<<<dim3(16, 32), 256>>>(1, opw, opb, out, 256);
    gemm_kernel<<<dim3(32, 32), 256>>>(2, ow, ob, out, 512);
}

// round 16
// speedup vs baseline: 1.1500x; 1.1500x over previous
#include <cuda_runtime.h>
#include <float.h>

#define DIM    256
#define BSEG   256
#define NSPLIT 4
#define CHUNK  32
#define PITCH  260   // floats per SMEM row; conflict-free LDS patterns

// ---------------- scratch (static device arrays; no cudaMalloc) ----------------
__device__ int   segStartG[BSEG + 1];             // precomputed segment boundaries
__device__ float qsG[DIM];                        // scaled q
__device__ float qkGf[4 * DIM];                   // final qk, [d][h] interleaved
__device__ float accPartG[NSPLIT * BSEG * 1024];  // raw per-quarter sums, [b*4+q][h*256+d]
__device__ float denomPartG[NSPLIT * BSEG * 4];   // raw per-quarter denoms, [b*4+q][h]
__device__ float pooledG[BSEG * DIM];
__device__ float attnG[BSEG * DIM];

// ---------------- P0: segment boundaries (sorted ids -> start offsets) ----------------
__global__ __launch_bounds__(256) void seg_bounds(const int* __restrict__ seg, int N) {
    int i = blockIdx.x * 256 + threadIdx.x;
    if (i >= N) return;
    int s = seg[i];
    if (i == 0) {
        for (int b = 0; b <= s; b++) segStartG[b] = 0;
    } else {
        int p = seg[i - 1];
        if (p != s)
            for (int b = p + 1; b <= s; b++) segStartG[b] = i;
    }
    if (i == N - 1)
        for (int b = s + 1; b <= BSEG; b++) segStartG[b] = N;
}

// ---------------- P1: q = ((gq @ Wq^T) + bq) * (1/sqrt(64)) ----------------
__global__ __launch_bounds__(256) void prologue_q(const float* __restrict__ ipw,
                                                  const float* __restrict__ ipb,
                                                  const float* __restrict__ gq) {
    __shared__ float gqs[DIM];
    int t = threadIdx.x;
    gqs[t] = gq[t];
    __syncthreads();
    int w = t >> 5, l = t & 31;
    int row = blockIdx.x * 8 + w;
    float sum = 0.f;
#pragma unroll
    for (int k = l; k < DIM; k += 32) sum += ipw[row * DIM + k] * gqs[k];
#pragma unroll
    for (int off = 16; off; off >>= 1) sum += __shfl_xor_sync(0xffffffffu, sum, off);
    if (l == 0) qsG[row] = (sum + ipb[row]) * 0.125f;
}

// ---------------- P2: qk[h][d] = sum_{j<64} qs[h*64+j] * Wk[h*64+j][d] ----------------
// (score bias bk cancels in softmax normalization)
__global__ __launch_bounds__(256) void prologue_qk(const float* __restrict__ ipw) {
    int h = blockIdx.x;                 // 4 blocks
    __shared__ float qsl[64];
    int t = threadIdx.x;
    if (t < 64) qsl[t] = qsG[h * 64 + t];
    __syncthreads();
    const float* W = ipw + (size_t)(DIM + h * 64) * DIM;
    float a = 0.f;
#pragma unroll 16
    for (int j = 0; j < 64; j++) a += qsl[j] * W[j * DIM + t];
    qkGf[t * 4 + h] = a;
}

// ---------------- main: R8 dataflow + register scores (no score-phase LDS) -----------
// No max subtraction (scores ~N(0,1): exp safe; max/bias cancel in normalization).
// Warp w owns nodes base+4w+j; thread (w,l) holds dims {4l..4l+3, 128+4l..+3} of them.
// Pipeline: STS -> register scores -> prefetch next chunk into SAME regs (Xs holds the
// data now) -> warp reduce/exp -> barrier -> rank-C from Xs -> barrier.
__global__ __launch_bounds__(256, 2) void seg_kernel(const float* __restrict__ X) {
    __shared__ __align__(16) float Xs[CHUNK * PITCH];  // 33.3 KB
    __shared__ float4 sp[8][4][4];    // [warp][lanegroup][node] score partials
    __shared__ float4 es4[CHUNK];     // per-node e (heads)
    __shared__ float4 dsm[8];         // per-warp denom

    int t = threadIdx.x, w = t >> 5, l = t & 31;
    int bid = blockIdx.x;
    int b = bid >> 2, quar = bid & 3;

    const float4* Q4 = (const float4*)qkGf;
    float4 qlo[4], qhi[4];
#pragma unroll
    for (int c = 0; c < 4; c++) { qlo[c] = Q4[4 * l + c]; qhi[c] = Q4[128 + 4 * l + c]; }

    int sLo = segStartG[b], sHi = segStartG[b + 1];
    int cnt = sHi - sLo;
    int lo = sLo + (cnt * quar) / NSPLIT;
    int hi = sLo + (cnt * (quar + 1)) / NSPLIT;

    float4 acc  = make_float4(0.f, 0.f, 0.f, 0.f);   // dim t, 4 heads
    float4 dacc = make_float4(0.f, 0.f, 0.f, 0.f);
    float4 R[4][2];
#pragma unroll
    for (int j = 0; j < 4; j++) {
        R[j][0] = make_float4(0.f, 0.f, 0.f, 0.f);
        R[j][1] = make_float4(0.f, 0.f, 0.f, 0.f);
    }

    const float4* Xg = (const float4*)X;
    int n0 = 4 * w;

    int base = lo;
    int C = (hi > lo) ? min(CHUNK, hi - lo) : 0;
    if (C > 0) {
#pragma unroll
        for (int j = 0; j < 4; j++) {
            int n = n0 + j;
            if (n < C) {
                R[j][0] = Xg[(size_t)(base + n) * 64 + l];
                R[j][1] = Xg[(size_t)(base + n) * 64 + 32 + l];
            }
        }
    }

    while (base < hi) {
        // ---- STS: warp's 4 nodes into Xs (conflict-free rows) ----
#pragma unroll
        for (int j = 0; j < 4; j++) {
            int n = n0 + j;
            if (n < C) {
                *(float4*)(Xs + n * PITCH + 4 * l)       = R[j][0];
                *(float4*)(Xs + n * PITCH + 128 + 4 * l) = R[j][1];
            }
        }
        // ---- register score partials (stale R beyond C is masked later by e=0) ----
        float4 ps[4];
#pragma unroll
        for (int j = 0; j < 4; j++) {
            float4 a = R[j][0], c4 = R[j][1];
            float4 s;
            s.x = a.x * qlo[0].x + a.y * qlo[1].x + a.z * qlo[2].x + a.w * qlo[3].x
                + c4.x * qhi[0].x + c4.y * qhi[1].x + c4.z * qhi[2].x + c4.w * qhi[3].x;
            s.y = a.x * qlo[0].y + a.y * qlo[1].y + a.z * qlo[2].y + a.w * qlo[3].y
                + c4.x * qhi[0].y + c4.y * qhi[1].y + c4.z * qhi[2].y + c4.w * qhi[3].y;
            s.z = a.x * qlo[0].z + a.y * qlo[1].z + a.z * qlo[2].z + a.w * qlo[3].z
                + c4.x * qhi[0].z + c4.y * qhi[1].z + c4.z * qhi[2].z + c4.w * qhi[3].z;
            s.w = a.x * qlo[0].w + a.y * qlo[1].w + a.z * qlo[2].w + a.w * qlo[3].w
                + c4.x * qhi[0].w + c4.y * qhi[1].w + c4.z * qhi[2].w + c4.w * qhi[3].w;
            ps[j] = s;
        }
        // ---- prefetch next chunk into the SAME regs (Xs now holds current chunk) ----
        // Consumed at next iteration's STS: hidden behind reduce + exp + rank-C.
        int baseN = base + CHUNK;
        int CN = 0;
        if (baseN < hi) {
            CN = min(CHUNK, hi - baseN);
#pragma unroll
            for (int j = 0; j < 4; j++) {
                int n = n0 + j;
                if (n < CN) {
                    R[j][0] = Xg[(size_t)(baseN + n) * 64 + l];
                    R[j][1] = Xg[(size_t)(baseN + n) * 64 + 32 + l];
                }
            }
        }
        // ---- 3-round butterfly: lane l holds sum over lanes = l (mod 4) ----
#pragma unroll
        for (int j = 0; j < 4; j++) {
#pragma unroll
            for (int off = 16; off >= 4; off >>= 1) {
                ps[j].x += __shfl_xor_sync(0xffffffffu, ps[j].x, off);
                ps[j].y += __shfl_xor_sync(0xffffffffu, ps[j].y, off);
                ps[j].z += __shfl_xor_sync(0xffffffffu, ps[j].z, off);
                ps[j].w += __shfl_xor_sync(0xffffffffu, ps[j].w, off);
            }
        }
        if (l < 4) {
#pragma unroll
            for (int j = 0; j < 4; j++) sp[w][l][j] = ps[j];
        }
        __syncwarp();
        if (l < 4) {   // lane l finishes node n0+l
            float4 s0 = sp[w][0][l], s1 = sp[w][1][l], s2 = sp[w][2][l], s3 = sp[w][3][l];
            float4 e;
            if (n0 + l < C) {
                e.x = __expf(s0.x + s1.x + s2.x + s3.x);
                e.y = __expf(s0.y + s1.y + s2.y + s3.y);
                e.z = __expf(s0.z + s1.z + s2.z + s3.z);
                e.w = __expf(s0.w + s1.w + s2.w + s3.w);
                dacc.x += e.x; dacc.y += e.y; dacc.z += e.z; dacc.w += e.w;
            } else {
                e = make_float4(0.f, 0.f, 0.f, 0.f);
            }
            es4[n0 + l] = e;
        }
        __syncthreads();   // Xs + es4 ready (CTA-wide)

        // ---- rank-C update: acc[h] += e[n][h] * X[n][d=t] ----
#pragma unroll 4
        for (int n = 0; n < C; n++) {
            float4 e4 = es4[n];              // broadcast
            float xv = Xs[n * PITCH + t];    // conflict-free
            acc.x += e4.x * xv;
            acc.y += e4.y * xv;
            acc.z += e4.z * xv;
            acc.w += e4.w * xv;
        }
        __syncthreads();   // protect Xs/es4 before next chunk's STS

        base = baseN;
        C = CN;
    }

    // ---- outputs: thread t owns dim t fully -> direct store, no cross-warp reduce ----
    float* Ap = accPartG + (size_t)bid * 1024;
    Ap[0 * DIM + t] = acc.x;
    Ap[1 * DIM + t] = acc.y;
    Ap[2 * DIM + t] = acc.z;
    Ap[3 * DIM + t] = acc.w;
    // denom: lanes 0-3 hold node-slot partials; xor 1,2 combine -> lane0 per warp
    dacc.x += __shfl_xor_sync(0xffffffffu, dacc.x, 1);
    dacc.y += __shfl_xor_sync(0xffffffffu, dacc.y, 1);
    dacc.z += __shfl_xor_sync(0xffffffffu, dacc.z, 1);
    dacc.w += __shfl_xor_sync(0xffffffffu, dacc.w, 1);
    dacc.x += __shfl_xor_sync(0xffffffffu, dacc.x, 2);
    dacc.y += __shfl_xor_sync(0xffffffffu, dacc.y, 2);
    dacc.z += __shfl_xor_sync(0xffffffffu, dacc.z, 2);
    dacc.w += __shfl_xor_sync(0xffffffffu, dacc.w, 2);
    if (l == 0) dsm[w] = dacc;
    __syncthreads();
    if (w == 0) {
        float4 v = (l < 8) ? dsm[l] : make_float4(0.f, 0.f, 0.f, 0.f);
#pragma unroll
        for (int off = 4; off; off >>= 1) {
            v.x += __shfl_xor_sync(0xffffffffu, v.x, off);
            v.y += __shfl_xor_sync(0xffffffffu, v.y, off);
            v.z += __shfl_xor_sync(0xffffffffu, v.z, off);
            v.w += __shfl_xor_sync(0xffffffffu, v.w, off);
        }
        if (l == 0) *(float4*)(denomPartG + bid * 4) = v;
    }
}

// ---------------- tiny GEMM: BM=8, BN=16, 2-way register split-K ----------------------
// mode 0: pooled = (sum of 4 quarter-partials, head-sliced)/denom @ Wv^T + bv
// mode 1: attn   = pooled @ Wo^T + opb
// mode 2: out    = attn @ Ww^T + ob  -> d_out
__global__ __launch_bounds__(256) void gemm_kernel(int mode,
                                                   const float* __restrict__ Wt,
                                                   const float* __restrict__ bias,
                                                   float* __restrict__ outp,
                                                   int Ncols) {
    __shared__ __align__(16) float As[8 * PITCH];    // 8.3 KB
    __shared__ __align__(16) float Ws[16 * PITCH];   // 16.6 KB
    int t = threadIdx.x;
    int c = t & 15, ks = (t >> 4) & 1, r = t >> 5;
    int nBase = blockIdx.x * 16, mBase = blockIdx.y * 8;

    if (mode == 0) {
        int hOff4 = (nBase >> 6) * 64;
#pragma unroll
        for (int i = 0; i < 2; i++) {
            int f = t + (i << 8);
            int m = f >> 6, k4 = f & 63;
            const float4* p0 = (const float4*)accPartG + (size_t)(mBase + m) * 1024 + hOff4 + k4;
            float4 a0 = p0[0], a1 = p0[256], a2 = p0[512], a3 = p0[768];
            float4 s = make_float4(a0.x + a1.x + a2.x + a3.x,
                                   a0.y + a1.y + a2.y + a3.y,
                                   a0.z + a1.z + a2.z + a3.z,
                                   a0.w + a1.w + a2.w + a3.w);
            *(float4*)(As + m * PITCH + 4 * k4) = s;
        }
    } else {
        const float* A = (mode == 1) ? pooledG : attnG;
#pragma unroll
        for (int i = 0; i < 2; i++) {
            int f = t + (i << 8);
            int m = f >> 6, k4 = f & 63;
            float4 a = ((const float4*)A)[(size_t)(mBase + m) * 64 + k4];
            *(float4*)(As + m * PITCH + 4 * k4) = a;
        }
    }
#pragma unroll
    for (int i = 0; i < 4; i++) {
        int f = t + (i << 8);
        int n = f >> 6, k4 = f & 63;
        float4 wv = ((const float4*)Wt)[(size_t)(nBase + n) * 64 + k4];
        *(float4*)(Ws + n * PITCH + 4 * k4) = wv;
    }
    __syncthreads();

    float acc = 0.f;
    int k0 = ks * 32;
#pragma unroll
    for (int k4 = 0; k4 < 32; k4++) {
        float4 a4 = *(const float4*)(As + r * PITCH + 4 * (k0 + k4));
        float4 w4 = *(const float4*)(Ws + c * PITCH + 4 * (k0 + k4));
        acc += a4.x * w4.x + a4.y * w4.y + a4.z * w4.z + a4.w * w4.w;
    }
    acc += __shfl_xor_sync(0xffffffffu, acc, 16);   // combine K halves

    if (ks == 0) {
        int row = mBase + r, col = nBase + c;
        if (mode == 0) {
            int h = nBase >> 6;
            float d = denomPartG[(row * 4 + 0) * 4 + h] + denomPartG[(row * 4 + 1) * 4 + h]
                    + denomPartG[(row * 4 + 2) * 4 + h] + denomPartG[(row * 4 + 3) * 4 + h];
            float inv = d > 0.f ? 1.f / d : 0.f;
            pooledG[row * DIM + col] = acc * inv + bias[col];
        } else if (mode == 1) {
            attnG[row * DIM + col] = acc + bias[col];
        } else {
            outp[(size_t)row * Ncols + col] = acc + bias[col];
        }
    }
}

// ---------------- launch (R15 resubmit #2: R13 design unchanged; broker infra error) --
extern "C" void kernel_launch(void* const* d_in, const int* in_sizes, int n_in,
                              void* d_out, int out_size) {
    const float* node_feat = (const float*)d_in[0];
    const int*   segids    = (const int*)d_in[1];
    const float* gq        = (const float*)d_in[2];
    const float* ipw       = (const float*)d_in[3];
    const float* ipb       = (const float*)d_in[4];
    const float* opw       = (const float*)d_in[5];
    const float* opb       = (const float*)d_in[6];
    const float* ow        = (const float*)d_in[7];
    const float* ob        = (const float*)d_in[8];
    int N = in_sizes[0] / DIM;
    float* out = (float*)d_out;

    seg_bounds<<<(N + 255) / 256, 256>>>(segids, N);
    prologue_q<<<32, 256>>>(ipw, ipb, gq);
    prologue_qk<<<4, 256>>>(ipw);
    seg_kernel<<<NSPLIT * BSEG, 256>>>(node_feat);
    gemm_kernel<<<dim3(16, 32), 256>>>(0, ipw + 512 * 256, ipb + 512, out, 256);
    gemm_kernel<<<dim3(16, 32), 256>>>(1, opw, opb, out, 256);
    gemm_kernel<<<dim3(32, 32), 256>>>(2, ow, ob, out, 512);
}